// round 1
// baseline (speedup 1.0000x reference)
#include <cuda_runtime.h>
#include <math_constants.h>

// ---------------------------------------------------------------------------
// AdaptiveAttention: B=2, S=2048, HS=1024, NH=16, HD=64, NP=8
// Round 1: fp32 baseline. All GEMMs via 128-wide smem-tiled SGEMM.
// ---------------------------------------------------------------------------

constexpr int cB = 2, cS = 2048, cHS = 1024, cNH = 16, cNP = 8, cHD = 64;
constexpr float cSCALE = 0.125f;  // 1/sqrt(64)
constexpr long OUT_ELEMS  = (long)cB * cS * cHS;        // 4,194,304
constexpr long ATTN_ELEMS = (long)cB * cNH * cS * cS;   // 134,217,728

// Scratch (device globals; allocation-free per harness rules)
__device__ float g_Q[(long)cB * cNH * cS * cHD];
__device__ float g_K[(long)cB * cNH * cS * cHD];
__device__ float g_V[(long)cB * cNH * cS * cHD];
__device__ float g_ctx[(long)cB * cS * cHS];
__device__ float g_pat[cB * cNH];
__device__ float g_attn_fallback[ATTN_ELEMS];  // used only if d_out lacks attn region

// ---------------------------------------------------------------------------
// Pattern selector: qmean -> relu(.@Wp1+bp1) -> softmax(.@Wp2+bp2) -> pat[b,h]
// One block per batch, 512 threads.
// ---------------------------------------------------------------------------
__global__ __launch_bounds__(512)
void pattern_kernel(const float* __restrict__ query,
                    const float* __restrict__ Wp1, const float* __restrict__ bp1,
                    const float* __restrict__ Wp2, const float* __restrict__ bp2,
                    const float* __restrict__ patterns)
{
    const int b = blockIdx.x;
    const int t = threadIdx.x;
    __shared__ float qm[cHS];
    __shared__ float hb[cHS / 2];
    __shared__ float pw[cNP];

    // mean over S for 2 columns per thread
    for (int c = t; c < cHS; c += 512) {
        const float* qp = query + (size_t)b * cS * cHS + c;
        float s = 0.f;
        for (int ss = 0; ss < cS; ss++) s += qp[(size_t)ss * cHS];
        qm[c] = s * (1.0f / cS);
    }
    __syncthreads();

    // h = relu(qmean @ Wp1 + bp1), 512 outputs
    {
        float a = bp1[t];
        for (int c = 0; c < cHS; c++) a += qm[c] * Wp1[c * (cHS / 2) + t];
        hb[t] = fmaxf(a, 0.f);
    }
    __syncthreads();

    __shared__ float lg[cNP];
    if (t < cNP) {
        float a = bp2[t];
        for (int j = 0; j < cHS / 2; j++) a += hb[j] * Wp2[j * cNP + t];
        lg[t] = a;
    }
    __syncthreads();
    if (t == 0) {
        float mx = lg[0];
        for (int p = 1; p < cNP; p++) mx = fmaxf(mx, lg[p]);
        float s = 0.f;
        for (int p = 0; p < cNP; p++) { pw[p] = __expf(lg[p] - mx); s += pw[p]; }
        float inv = 1.0f / s;
        for (int p = 0; p < cNP; p++) pw[p] *= inv;
    }
    __syncthreads();
    if (t < cNH) {
        float a = 0.f;
        for (int p = 0; p < cNP; p++) a += pw[p] * patterns[p * cNH + t];
        g_pat[b * cNH + t] = a;
    }
}

// ---------------------------------------------------------------------------
// Generic 128x128x16 SGEMM: C = A[M,K] @ W[K,N] + bias[N]
// MODE 0: plain row-major store. MODE 1: scatter into [B,NH,S,HD] (QKV).
// ---------------------------------------------------------------------------
template <int MODE>
__global__ __launch_bounds__(256)
void gemm128(const float* __restrict__ A, const float* __restrict__ W,
             const float* __restrict__ bias, float* __restrict__ C,
             int M, int N, int K)
{
    __shared__ float As[16][132];  // padded to reduce store conflicts
    __shared__ float Bs[16][128];
    const int m0 = blockIdx.y * 128;
    const int n0 = blockIdx.x * 128;
    const int t = threadIdx.x;
    const int tx = t & 15, ty = t >> 4;

    float acc[8][8];
#pragma unroll
    for (int i = 0; i < 8; i++)
#pragma unroll
        for (int j = 0; j < 8; j++) acc[i][j] = 0.f;

    for (int k0 = 0; k0 < K; k0 += 16) {
#pragma unroll
        for (int i = 0; i < 8; i++) {
            int lin = t + i * 256;
            int m = lin >> 4, k = lin & 15;
            As[k][m] = A[(size_t)(m0 + m) * K + k0 + k];
            int kb = lin >> 7, nb = lin & 127;
            Bs[kb][nb] = W[(size_t)(k0 + kb) * N + n0 + nb];
        }
        __syncthreads();
#pragma unroll
        for (int k = 0; k < 16; k++) {
            float4 a0 = *(const float4*)&As[k][ty * 4];
            float4 a1 = *(const float4*)&As[k][64 + ty * 4];
            float4 b0 = *(const float4*)&Bs[k][tx * 4];
            float4 b1 = *(const float4*)&Bs[k][64 + tx * 4];
            float av[8] = {a0.x, a0.y, a0.z, a0.w, a1.x, a1.y, a1.z, a1.w};
            float bv[8] = {b0.x, b0.y, b0.z, b0.w, b1.x, b1.y, b1.z, b1.w};
#pragma unroll
            for (int i = 0; i < 8; i++)
#pragma unroll
                for (int j = 0; j < 8; j++) acc[i][j] += av[i] * bv[j];
        }
        __syncthreads();
    }

#pragma unroll
    for (int i = 0; i < 8; i++) {
        int m = m0 + ((i < 4) ? (ty * 4 + i) : (64 + ty * 4 + i - 4));
#pragma unroll
        for (int j = 0; j < 8; j++) {
            int n = n0 + ((j < 4) ? (tx * 4 + j) : (64 + tx * 4 + j - 4));
            float v = acc[i][j] + bias[n];
            if (MODE == 0) {
                C[(size_t)m * N + n] = v;
            } else {
                int b = m / cS, s = m - b * cS;
                int h = n / cHD, d = n - h * cHD;
                C[(((size_t)(b * cNH + h)) * cS + s) * cHD + d] = v;
            }
        }
    }
}

// ---------------------------------------------------------------------------
// Scores: attn[bh,q,k] = (Q . K) * SCALE * pat[bh], masked to -1e9
// 128x128 tiles over [S,S], K-dim = HD = 64
// ---------------------------------------------------------------------------
__global__ __launch_bounds__(256)
void scores_kernel(const int* __restrict__ mask, float* __restrict__ attn)
{
    __shared__ float As[16][132];
    __shared__ float Bs[16][132];
    const int bh = blockIdx.z;
    const int b = bh >> 4;
    const float* Qm = g_Q + (size_t)bh * cS * cHD;
    const float* Km = g_K + (size_t)bh * cS * cHD;
    const float patv = g_pat[bh] * cSCALE;
    const int m0 = blockIdx.y * 128;
    const int n0 = blockIdx.x * 128;
    const int t = threadIdx.x;
    const int tx = t & 15, ty = t >> 4;

    float acc[8][8];
#pragma unroll
    for (int i = 0; i < 8; i++)
#pragma unroll
        for (int j = 0; j < 8; j++) acc[i][j] = 0.f;

    for (int k0 = 0; k0 < cHD; k0 += 16) {
#pragma unroll
        for (int i = 0; i < 8; i++) {
            int lin = t + i * 256;
            int m = lin >> 4, k = lin & 15;
            As[k][m] = Qm[(size_t)(m0 + m) * cHD + k0 + k];
            Bs[k][m] = Km[(size_t)(n0 + m) * cHD + k0 + k];
        }
        __syncthreads();
#pragma unroll
        for (int k = 0; k < 16; k++) {
            float4 a0 = *(const float4*)&As[k][ty * 4];
            float4 a1 = *(const float4*)&As[k][64 + ty * 4];
            float4 b0 = *(const float4*)&Bs[k][tx * 4];
            float4 b1 = *(const float4*)&Bs[k][64 + tx * 4];
            float av[8] = {a0.x, a0.y, a0.z, a0.w, a1.x, a1.y, a1.z, a1.w};
            float bv[8] = {b0.x, b0.y, b0.z, b0.w, b1.x, b1.y, b1.z, b1.w};
#pragma unroll
            for (int i = 0; i < 8; i++)
#pragma unroll
                for (int j = 0; j < 8; j++) acc[i][j] += av[i] * bv[j];
        }
        __syncthreads();
    }

    const int* mrow = mask + (size_t)b * cS * cS;
    float* arow = attn + (size_t)bh * cS * cS;
#pragma unroll
    for (int i = 0; i < 8; i++) {
        int q = m0 + ((i < 4) ? (ty * 4 + i) : (64 + ty * 4 + i - 4));
#pragma unroll
        for (int j = 0; j < 8; j++) {
            int kk = n0 + ((j < 4) ? (tx * 4 + j) : (64 + tx * 4 + j - 4));
            float v = acc[i][j] * patv;
            if (mrow[(size_t)q * cS + kk] == 0) v = -1e9f;
            arow[(size_t)q * cS + kk] = v;
        }
    }
}

// ---------------------------------------------------------------------------
// Row softmax over last dim (S=2048), one block per row
// ---------------------------------------------------------------------------
__global__ __launch_bounds__(256)
void softmax_kernel(float* __restrict__ attn)
{
    const size_t row = blockIdx.x;
    float* p = attn + row * cS;
    const int t = threadIdx.x;
    float v[8];
    float mx = -CUDART_INF_F;
#pragma unroll
    for (int i = 0; i < 8; i++) { v[i] = p[t + i * 256]; mx = fmaxf(mx, v[i]); }

    __shared__ float red[256];
    red[t] = mx;
    __syncthreads();
    for (int s2 = 128; s2 > 0; s2 >>= 1) {
        if (t < s2) red[t] = fmaxf(red[t], red[t + s2]);
        __syncthreads();
    }
    mx = red[0];
    __syncthreads();

    float sum = 0.f;
#pragma unroll
    for (int i = 0; i < 8; i++) { v[i] = __expf(v[i] - mx); sum += v[i]; }
    red[t] = sum;
    __syncthreads();
    for (int s2 = 128; s2 > 0; s2 >>= 1) {
        if (t < s2) red[t] += red[t + s2];
        __syncthreads();
    }
    float inv = 1.0f / red[0];
#pragma unroll
    for (int i = 0; i < 8; i++) p[t + i * 256] = v[i] * inv;
}

// ---------------------------------------------------------------------------
// Context: ctx[b,s, h*HD+d] = sum_k attn[bh,s,k] * V[bh,k,d]
// 128(M) x 64(N) tiles, K = S = 2048
// ---------------------------------------------------------------------------
__global__ __launch_bounds__(256)
void context_kernel(const float* __restrict__ attn)
{
    __shared__ float As[16][132];
    __shared__ float Bs[16][64];
    const int bh = blockIdx.z;
    const int b = bh >> 4, h = bh & 15;
    const float* Am = attn + (size_t)bh * cS * cS;
    const float* Vm = g_V + (size_t)bh * cS * cHD;
    const int m0 = blockIdx.y * 128;
    const int t = threadIdx.x;
    const int tx = t & 15, ty = t >> 4;

    float acc[8][4];
#pragma unroll
    for (int i = 0; i < 8; i++)
#pragma unroll
        for (int j = 0; j < 4; j++) acc[i][j] = 0.f;

    for (int k0 = 0; k0 < cS; k0 += 16) {
#pragma unroll
        for (int i = 0; i < 8; i++) {
            int lin = t + i * 256;
            int m = lin >> 4, k = lin & 15;
            As[k][m] = Am[(size_t)(m0 + m) * cS + k0 + k];
        }
#pragma unroll
        for (int i = 0; i < 4; i++) {
            int lin = t + i * 256;
            int kb = lin >> 6, nb = lin & 63;
            Bs[kb][nb] = Vm[(size_t)(k0 + kb) * cHD + nb];
        }
        __syncthreads();
#pragma unroll
        for (int k = 0; k < 16; k++) {
            float4 a0 = *(const float4*)&As[k][ty * 4];
            float4 a1 = *(const float4*)&As[k][64 + ty * 4];
            float4 b0 = *(const float4*)&Bs[k][tx * 4];
            float av[8] = {a0.x, a0.y, a0.z, a0.w, a1.x, a1.y, a1.z, a1.w};
            float bv[4] = {b0.x, b0.y, b0.z, b0.w};
#pragma unroll
            for (int i = 0; i < 8; i++)
#pragma unroll
                for (int j = 0; j < 4; j++) acc[i][j] += av[i] * bv[j];
        }
        __syncthreads();
    }

#pragma unroll
    for (int i = 0; i < 8; i++) {
        int s = m0 + ((i < 4) ? (ty * 4 + i) : (64 + ty * 4 + i - 4));
#pragma unroll
        for (int j = 0; j < 4; j++) {
            int d = tx * 4 + j;
            g_ctx[(size_t)(b * cS + s) * cHS + h * cHD + d] = acc[i][j];
        }
    }
}

// ---------------------------------------------------------------------------
// kernel_launch
// Inputs (metadata order): query, key, value, attention_mask,
//   Wq, bq, Wk, bk, Wv, bv, Wo, bo, Wp1, bp1, Wp2, bp2, patterns
// Output: [output (B,S,HS) fp32][attn_weights (B,NH,S,S) fp32] if out_size
//   covers both; otherwise only output, attn kept in fallback scratch.
// ---------------------------------------------------------------------------
extern "C" void kernel_launch(void* const* d_in, const int* in_sizes, int n_in,
                              void* d_out, int out_size)
{
    const float* query = (const float*)d_in[0];
    const float* key   = (const float*)d_in[1];
    const float* value = (const float*)d_in[2];
    const int*   mask  = (const int*)d_in[3];
    const float* Wq  = (const float*)d_in[4];  const float* bq  = (const float*)d_in[5];
    const float* Wk  = (const float*)d_in[6];  const float* bk  = (const float*)d_in[7];
    const float* Wv  = (const float*)d_in[8];  const float* bv  = (const float*)d_in[9];
    const float* Wo  = (const float*)d_in[10]; const float* bo  = (const float*)d_in[11];
    const float* Wp1 = (const float*)d_in[12]; const float* bp1 = (const float*)d_in[13];
    const float* Wp2 = (const float*)d_in[14]; const float* bp2 = (const float*)d_in[15];
    const float* patterns = (const float*)d_in[16];
    float* out = (float*)d_out;

    // scratch pointers
    void *pQ, *pK, *pV;
    cudaGetSymbolAddress(&pQ, g_Q);
    cudaGetSymbolAddress(&pK, g_K);
    cudaGetSymbolAddress(&pV, g_V);
    void* pCtx;
    cudaGetSymbolAddress(&pCtx, g_ctx);

    float* attn;
    if ((long)out_size >= OUT_ELEMS + ATTN_ELEMS) {
        attn = out + OUT_ELEMS;  // write attn_weights directly into d_out
    } else {
        void* pa;
        cudaGetSymbolAddress(&pa, g_attn_fallback);
        attn = (float*)pa;
    }

    // 1. pattern selector (per-(b,h) scale)
    pattern_kernel<<<cB, 512>>>(query, Wp1, bp1, Wp2, bp2, patterns);

    // 2. QKV projections -> [B,NH,S,HD]
    dim3 gProj(cHS / 128, (cB * cS) / 128);  // (8, 32)
    gemm128<1><<<gProj, 256>>>(query, Wq, bq, (float*)pQ, cB * cS, cHS, cHS);
    gemm128<1><<<gProj, 256>>>(key,   Wk, bk, (float*)pK, cB * cS, cHS, cHS);
    gemm128<1><<<gProj, 256>>>(value, Wv, bv, (float*)pV, cB * cS, cHS, cHS);

    // 3. scores (scaled, pattern-weighted, masked)
    dim3 gScores(cS / 128, cS / 128, cB * cNH);  // (16, 16, 32)
    scores_kernel<<<gScores, 256>>>(mask, attn);

    // 4. softmax over rows
    softmax_kernel<<<cB * cNH * cS, 256>>>(attn);

    // 5. context = attn @ V, stored as [B,S,HS]
    dim3 gCtx(1, cS / 128, cB * cNH);  // (1, 16, 32)
    context_kernel<<<gCtx, 256>>>(attn);

    // 6. output projection
    dim3 gOut(cHS / 128, (cB * cS) / 128);
    gemm128<0><<<gOut, 256>>>((const float*)pCtx, Wo, bo, out, cB * cS, cHS, cHS);
}

// round 6
// speedup vs baseline: 1.6418x; 1.6418x over previous
#include <cuda_runtime.h>
#include <cstdint>
#include <math_constants.h>

// ---------------------------------------------------------------------------
// AdaptiveAttention: B=2, S=2048, HS=1024, NH=16, HD=64, NP=8
// Round 6: mma.sync tf32 with 3xTF32 error compensation (near-fp32 accuracy).
// ---------------------------------------------------------------------------

constexpr int cB = 2, cS = 2048, cHS = 1024, cNH = 16, cNP = 8, cHD = 64;
constexpr float cSCALE = 0.125f;  // 1/sqrt(64)
constexpr long OUT_ELEMS  = (long)cB * cS * cHS;        // 4,194,304
constexpr long ATTN_ELEMS = (long)cB * cNH * cS * cS;   // 134,217,728

// Scratch (device globals; allocation-free per harness rules)
__device__ float g_Q[(long)cB * cNH * cS * cHD];
__device__ float g_K[(long)cB * cNH * cS * cHD];
__device__ float g_V[(long)cB * cNH * cS * cHD];     // [b,h,s,d]
__device__ float g_ctx[(long)cB * cS * cHS];
__device__ float g_pat[cB * cNH];
__device__ float g_WT[4L * cHS * cHS];               // transposed weights [N,K] x4
__device__ float g_qpart[32 * cHS];
__device__ float g_attn_fallback[ATTN_ELEMS];

// ---------------------------------------------------------------------------
// PTX helpers (baseline ISA only — tcgen05 unavailable on this toolchain)
// ---------------------------------------------------------------------------
__device__ __forceinline__ uint32_t smem_u32(const void* p) {
    uint32_t a;
    asm("{ .reg .u64 t; cvta.to.shared.u64 t, %1; cvt.u32.u64 %0, t; }" : "=r"(a) : "l"(p));
    return a;
}
#define CP_ASYNC16(dst, src) \
    asm volatile("cp.async.cg.shared.global [%0], [%1], 16;" :: "r"(dst), "l"(src))
#define CP_COMMIT() asm volatile("cp.async.commit_group;")
#define CP_WAIT(n)  asm volatile("cp.async.wait_group %0;" :: "n"(n))

__device__ __forceinline__ void mma_tf32(float c[4], const uint32_t a[4], const uint32_t b[2]) {
    asm volatile(
        "mma.sync.aligned.m16n8k8.row.col.f32.tf32.tf32.f32 "
        "{%0,%1,%2,%3}, {%4,%5,%6,%7}, {%8,%9}, {%0,%1,%2,%3};"
        : "+f"(c[0]), "+f"(c[1]), "+f"(c[2]), "+f"(c[3])
        : "r"(a[0]), "r"(a[1]), "r"(a[2]), "r"(a[3]), "r"(b[0]), "r"(b[1]));
}

// 3xTF32 split: x = hi + lo, both tf32-representable; hi exact in fp32.
__device__ __forceinline__ void splitf(float x, uint32_t& hi, uint32_t& lo) {
    asm("cvt.rna.tf32.f32 %0, %1;" : "=r"(hi) : "f"(x));
    float r = x - __uint_as_float(hi);
    asm("cvt.rna.tf32.f32 %0, %1;" : "=r"(lo) : "f"(r));
}

// ===========================================================================
// gemm_mma: C = A[M,1024] @ Bt^T + bias.  Bt is [N,K] K-major.
// Block tile 128x128, K-chunk 32, cp.async double-buffered smem (stride 36).
// 8 warps: 4(m) x 2(n), warp tile 32x64. 3xTF32 per fragment pair.
// MODE 0: row-major [M,N] store. MODE 1: scatter [B,NH,S,HD].
// ===========================================================================
template <int MODE>
__global__ __launch_bounds__(256)
void gemm_mma(const float* __restrict__ A, const float* __restrict__ Bt,
              const float* __restrict__ bias, float* __restrict__ C)
{
    extern __shared__ float sm[];
    float* As = sm;                   // [2][128*36]
    float* Bs = sm + 2 * 128 * 36;    // [2][128*36]
    const uint32_t sA = smem_u32(As), sB = smem_u32(Bs);
    const int t = threadIdx.x, lane = t & 31, wid = t >> 5;
    const int wm = wid >> 1, wn = wid & 1;
    const int gid = lane >> 2, tig = lane & 3;
    const int m0 = blockIdx.y * 128, n0 = blockIdx.x * 128;

    float c[2][8][4] = {};

    // issue chunk 0
#pragma unroll
    for (int i = 0; i < 4; i++) {
        int idx = t + i * 256, r = idx >> 3, kq = idx & 7;
        CP_ASYNC16(sA + (r * 36 + kq * 4) * 4, &A[(size_t)(m0 + r) * 1024 + kq * 4]);
        CP_ASYNC16(sB + (r * 36 + kq * 4) * 4, &Bt[(size_t)(n0 + r) * 1024 + kq * 4]);
    }
    CP_COMMIT();

    const int T = 32;
    for (int ch = 0; ch < T; ch++) {
        const int cur = ch & 1;
        if (ch + 1 < T) {
            const uint32_t off = (uint32_t)((cur ^ 1) * 128 * 36) * 4;
#pragma unroll
            for (int i = 0; i < 4; i++) {
                int idx = t + i * 256, r = idx >> 3, kq = idx & 7;
                CP_ASYNC16(sA + off + (r * 36 + kq * 4) * 4,
                           &A[(size_t)(m0 + r) * 1024 + (ch + 1) * 32 + kq * 4]);
                CP_ASYNC16(sB + off + (r * 36 + kq * 4) * 4,
                           &Bt[(size_t)(n0 + r) * 1024 + (ch + 1) * 32 + kq * 4]);
            }
            CP_COMMIT();
            CP_WAIT(1);
        } else {
            CP_WAIT(0);
        }
        __syncthreads();

        const float* Ab = As + cur * 128 * 36;
        const float* Bb = Bs + cur * 128 * 36;
#pragma unroll
        for (int kk = 0; kk < 4; kk++) {
            uint32_t ah[2][4], al[2][4], bh[8][2], bl[8][2];
#pragma unroll
            for (int mi = 0; mi < 2; mi++) {
                int r = wm * 32 + mi * 16 + gid;
                splitf(Ab[r * 36 + kk * 8 + tig],           ah[mi][0], al[mi][0]);
                splitf(Ab[(r + 8) * 36 + kk * 8 + tig],     ah[mi][1], al[mi][1]);
                splitf(Ab[r * 36 + kk * 8 + tig + 4],       ah[mi][2], al[mi][2]);
                splitf(Ab[(r + 8) * 36 + kk * 8 + tig + 4], ah[mi][3], al[mi][3]);
            }
#pragma unroll
            for (int ni = 0; ni < 8; ni++) {
                int n = wn * 64 + ni * 8 + gid;
                splitf(Bb[n * 36 + kk * 8 + tig],     bh[ni][0], bl[ni][0]);
                splitf(Bb[n * 36 + kk * 8 + tig + 4], bh[ni][1], bl[ni][1]);
            }
#pragma unroll
            for (int mi = 0; mi < 2; mi++)
#pragma unroll
                for (int ni = 0; ni < 8; ni++) {
                    mma_tf32(c[mi][ni], al[mi], bh[ni]);
                    mma_tf32(c[mi][ni], ah[mi], bl[ni]);
                    mma_tf32(c[mi][ni], ah[mi], bh[ni]);
                }
        }
        __syncthreads();
    }

#pragma unroll
    for (int mi = 0; mi < 2; mi++)
#pragma unroll
        for (int half = 0; half < 2; half++) {
            int m = m0 + wm * 32 + mi * 16 + gid + half * 8;
            int b = m >> 11, s = m & 2047;
#pragma unroll
            for (int ni = 0; ni < 8; ni++) {
                int n = n0 + wn * 64 + ni * 8 + tig * 2;
                float2 v;
                v.x = c[mi][ni][half * 2 + 0] + bias[n];
                v.y = c[mi][ni][half * 2 + 1] + bias[n + 1];
                if (MODE == 0) {
                    *(float2*)&C[(size_t)m * 1024 + n] = v;
                } else {
                    int h = n >> 6, d = n & 63;
                    *(float2*)&C[(((size_t)(b * cNH + h) * cS + s) * cHD) + d] = v;
                }
            }
        }
}

// ===========================================================================
// scores_mma: attn[bh,q,k] = (Q.K)*SCALE*pat, masked. 128x128 tile, K=64.
// ===========================================================================
__global__ __launch_bounds__(256)
void scores_mma(const int* __restrict__ mask, float* __restrict__ attn)
{
    extern __shared__ float sm[];
    float* As = sm;              // 128*68
    float* Bs = sm + 128 * 68;
    const uint32_t sA = smem_u32(As), sB = smem_u32(Bs);
    const int t = threadIdx.x, lane = t & 31, wid = t >> 5;
    const int wm = wid >> 1, wn = wid & 1;
    const int gid = lane >> 2, tig = lane & 3;
    const int bh = blockIdx.z, b = bh >> 4;
    const int q0 = blockIdx.y * 128, n0 = blockIdx.x * 128;
    const float* Qm = g_Q + (size_t)bh * cS * cHD;
    const float* Km = g_K + (size_t)bh * cS * cHD;

#pragma unroll
    for (int i = 0; i < 8; i++) {
        int idx = t + i * 256, r = idx >> 4, kq = idx & 15;
        CP_ASYNC16(sA + (r * 68 + kq * 4) * 4, &Qm[(size_t)(q0 + r) * 64 + kq * 4]);
        CP_ASYNC16(sB + (r * 68 + kq * 4) * 4, &Km[(size_t)(n0 + r) * 64 + kq * 4]);
    }
    CP_COMMIT();
    CP_WAIT(0);
    __syncthreads();

    float c[2][8][4] = {};
#pragma unroll
    for (int kk = 0; kk < 8; kk++) {
        uint32_t ah[2][4], al[2][4], bh[8][2], bl[8][2];
#pragma unroll
        for (int mi = 0; mi < 2; mi++) {
            int r = wm * 32 + mi * 16 + gid;
            splitf(As[r * 68 + kk * 8 + tig],           ah[mi][0], al[mi][0]);
            splitf(As[(r + 8) * 68 + kk * 8 + tig],     ah[mi][1], al[mi][1]);
            splitf(As[r * 68 + kk * 8 + tig + 4],       ah[mi][2], al[mi][2]);
            splitf(As[(r + 8) * 68 + kk * 8 + tig + 4], ah[mi][3], al[mi][3]);
        }
#pragma unroll
        for (int ni = 0; ni < 8; ni++) {
            int n = wn * 64 + ni * 8 + gid;
            splitf(Bs[n * 68 + kk * 8 + tig],     bh[ni][0], bl[ni][0]);
            splitf(Bs[n * 68 + kk * 8 + tig + 4], bh[ni][1], bl[ni][1]);
        }
#pragma unroll
        for (int mi = 0; mi < 2; mi++)
#pragma unroll
            for (int ni = 0; ni < 8; ni++) {
                mma_tf32(c[mi][ni], al[mi], bh[ni]);
                mma_tf32(c[mi][ni], ah[mi], bl[ni]);
                mma_tf32(c[mi][ni], ah[mi], bh[ni]);
            }
    }

    const float patv = g_pat[bh] * cSCALE;
    const size_t mbase = (size_t)b * cS * cS;
    const size_t abase = (size_t)bh * cS * cS;
#pragma unroll
    for (int mi = 0; mi < 2; mi++)
#pragma unroll
        for (int half = 0; half < 2; half++) {
            int q = q0 + wm * 32 + mi * 16 + gid + half * 8;
#pragma unroll
            for (int ni = 0; ni < 8; ni++) {
                int col = n0 + wn * 64 + ni * 8 + tig * 2;
                float2 v;
                v.x = c[mi][ni][half * 2 + 0] * patv;
                v.y = c[mi][ni][half * 2 + 1] * patv;
                int2 mk = *(const int2*)&mask[mbase + (size_t)q * cS + col];
                if (mk.x == 0) v.x = -1e9f;
                if (mk.y == 0) v.y = -1e9f;
                *(float2*)&attn[abase + (size_t)q * cS + col] = v;
            }
        }
}

// ===========================================================================
// context_mma: ctx[b,s,h*64+d] = sum_k attn[bh,s,k] * V[bh,k,d]
// Block tile 128x64, K=2048 (chunks 32, double buffered; A via cp.async,
// V transposed through registers). 8 warps 4x2, warp tile 32x32. 3xTF32.
// ===========================================================================
__global__ __launch_bounds__(256)
void context_mma(const float* __restrict__ attn)
{
    extern __shared__ float sm[];
    float* As = sm;                   // [2][128*36]
    float* Bs = sm + 2 * 128 * 36;    // [2][64*36]
    const uint32_t sA = smem_u32(As);
    const int t = threadIdx.x, lane = t & 31, wid = t >> 5;
    const int wm = wid >> 1, wn = wid & 1;
    const int gid = lane >> 2, tig = lane & 3;
    const int bh = blockIdx.y, q0 = blockIdx.x * 128;
    const int b = bh >> 4, h = bh & 15;
    const float* Am = attn + (size_t)bh * cS * cS;
    const float* Vm = g_V + (size_t)bh * cS * cHD;

    float c[2][4][4] = {};

    // chunk 0: A via cp.async, V via registers (transposed store)
#pragma unroll
    for (int i = 0; i < 4; i++) {
        int idx = t + i * 256, r = idx >> 3, kq = idx & 7;
        CP_ASYNC16(sA + (r * 36 + kq * 4) * 4, &Am[(size_t)(q0 + r) * cS + kq * 4]);
    }
    CP_COMMIT();
#pragma unroll
    for (int i = 0; i < 2; i++) {
        int idx = t + i * 256, sl = idx >> 4, dq = idx & 15;
        float4 v = *(const float4*)&Vm[(size_t)sl * 64 + dq * 4];
        Bs[(dq * 4 + 0) * 36 + sl] = v.x;
        Bs[(dq * 4 + 1) * 36 + sl] = v.y;
        Bs[(dq * 4 + 2) * 36 + sl] = v.z;
        Bs[(dq * 4 + 3) * 36 + sl] = v.w;
    }

    const int T = 64;
    float4 rB[2];
    for (int ch = 0; ch < T; ch++) {
        const int cur = ch & 1;
        if (ch + 1 < T) {
            const uint32_t off = (uint32_t)((cur ^ 1) * 128 * 36) * 4;
#pragma unroll
            for (int i = 0; i < 4; i++) {
                int idx = t + i * 256, r = idx >> 3, kq = idx & 7;
                CP_ASYNC16(sA + off + (r * 36 + kq * 4) * 4,
                           &Am[(size_t)(q0 + r) * cS + (ch + 1) * 32 + kq * 4]);
            }
            CP_COMMIT();
#pragma unroll
            for (int i = 0; i < 2; i++) {
                int idx = t + i * 256, sl = idx >> 4, dq = idx & 15;
                rB[i] = *(const float4*)&Vm[(size_t)((ch + 1) * 32 + sl) * 64 + dq * 4];
            }
            CP_WAIT(1);
        } else {
            CP_WAIT(0);
        }
        __syncthreads();

        const float* Ab = As + cur * 128 * 36;
        const float* Bb = Bs + cur * 64 * 36;
#pragma unroll
        for (int kk = 0; kk < 4; kk++) {
            uint32_t ah[2][4], al[2][4], bh2[4][2], bl2[4][2];
#pragma unroll
            for (int mi = 0; mi < 2; mi++) {
                int r = wm * 32 + mi * 16 + gid;
                splitf(Ab[r * 36 + kk * 8 + tig],           ah[mi][0], al[mi][0]);
                splitf(Ab[(r + 8) * 36 + kk * 8 + tig],     ah[mi][1], al[mi][1]);
                splitf(Ab[r * 36 + kk * 8 + tig + 4],       ah[mi][2], al[mi][2]);
                splitf(Ab[(r + 8) * 36 + kk * 8 + tig + 4], ah[mi][3], al[mi][3]);
            }
#pragma unroll
            for (int ni = 0; ni < 4; ni++) {
                int n = wn * 32 + ni * 8 + gid;
                splitf(Bb[n * 36 + kk * 8 + tig],     bh2[ni][0], bl2[ni][0]);
                splitf(Bb[n * 36 + kk * 8 + tig + 4], bh2[ni][1], bl2[ni][1]);
            }
#pragma unroll
            for (int mi = 0; mi < 2; mi++)
#pragma unroll
                for (int ni = 0; ni < 4; ni++) {
                    mma_tf32(c[mi][ni], al[mi], bh2[ni]);
                    mma_tf32(c[mi][ni], ah[mi], bl2[ni]);
                    mma_tf32(c[mi][ni], ah[mi], bh2[ni]);
                }
        }
        __syncthreads();
        if (ch + 1 < T) {
            float* Bw = Bs + (cur ^ 1) * 64 * 36;
#pragma unroll
            for (int i = 0; i < 2; i++) {
                int idx = t + i * 256, sl = idx >> 4, dq = idx & 15;
                Bw[(dq * 4 + 0) * 36 + sl] = rB[i].x;
                Bw[(dq * 4 + 1) * 36 + sl] = rB[i].y;
                Bw[(dq * 4 + 2) * 36 + sl] = rB[i].z;
                Bw[(dq * 4 + 3) * 36 + sl] = rB[i].w;
            }
        }
    }

#pragma unroll
    for (int mi = 0; mi < 2; mi++)
#pragma unroll
        for (int half = 0; half < 2; half++) {
            int s = q0 + wm * 32 + mi * 16 + gid + half * 8;
#pragma unroll
            for (int ni = 0; ni < 4; ni++) {
                int n = wn * 32 + ni * 8 + tig * 2;
                float2 v;
                v.x = c[mi][ni][half * 2 + 0];
                v.y = c[mi][ni][half * 2 + 1];
                *(float2*)&g_ctx[((size_t)(b * cS + s)) * cHS + h * cHD + n] = v;
            }
        }
}

// ===========================================================================
// Softmax over rows of attn (S=2048), float4 vectorized.
// ===========================================================================
__global__ __launch_bounds__(256)
void softmax_k(float* __restrict__ attn)
{
    const size_t row = blockIdx.x;
    float4* p = (float4*)(attn + row * cS);
    const int t = threadIdx.x;
    float4 v0 = p[t], v1 = p[t + 256];
    float mx = fmaxf(fmaxf(fmaxf(v0.x, v0.y), fmaxf(v0.z, v0.w)),
                     fmaxf(fmaxf(v1.x, v1.y), fmaxf(v1.z, v1.w)));
    __shared__ float red[8];
#pragma unroll
    for (int o = 16; o > 0; o >>= 1) mx = fmaxf(mx, __shfl_xor_sync(0xffffffff, mx, o));
    if ((t & 31) == 0) red[t >> 5] = mx;
    __syncthreads();
    mx = fmaxf(fmaxf(fmaxf(red[0], red[1]), fmaxf(red[2], red[3])),
               fmaxf(fmaxf(red[4], red[5]), fmaxf(red[6], red[7])));
    v0.x = __expf(v0.x - mx); v0.y = __expf(v0.y - mx);
    v0.z = __expf(v0.z - mx); v0.w = __expf(v0.w - mx);
    v1.x = __expf(v1.x - mx); v1.y = __expf(v1.y - mx);
    v1.z = __expf(v1.z - mx); v1.w = __expf(v1.w - mx);
    float sm = v0.x + v0.y + v0.z + v0.w + v1.x + v1.y + v1.z + v1.w;
#pragma unroll
    for (int o = 16; o > 0; o >>= 1) sm += __shfl_xor_sync(0xffffffff, sm, o);
    __shared__ float red2[8];
    if ((t & 31) == 0) red2[t >> 5] = sm;
    __syncthreads();
    sm = red2[0] + red2[1] + red2[2] + red2[3] + red2[4] + red2[5] + red2[6] + red2[7];
    float inv = 1.0f / sm;
    v0.x *= inv; v0.y *= inv; v0.z *= inv; v0.w *= inv;
    v1.x *= inv; v1.y *= inv; v1.z *= inv; v1.w *= inv;
    p[t] = v0; p[t + 256] = v1;
}

// ===========================================================================
// Weight transpose: g_WT[z][n][k] = W_z[k][n]
// ===========================================================================
__global__ void transpose_w(const float* __restrict__ W0, const float* __restrict__ W1,
                            const float* __restrict__ W2, const float* __restrict__ W3)
{
    __shared__ float tile[32][33];
    const float* W = blockIdx.z == 0 ? W0 : blockIdx.z == 1 ? W1 : blockIdx.z == 2 ? W2 : W3;
    float* O = g_WT + (size_t)blockIdx.z * cHS * cHS;
    int x = blockIdx.x * 32 + threadIdx.x;
    int y0 = blockIdx.y * 32;
#pragma unroll
    for (int i = 0; i < 4; i++)
        tile[threadIdx.y + i * 8][threadIdx.x] = W[(size_t)(y0 + threadIdx.y + i * 8) * cHS + x];
    __syncthreads();
    int nx = blockIdx.y * 32 + threadIdx.x;
    int ny0 = blockIdx.x * 32;
#pragma unroll
    for (int i = 0; i < 4; i++)
        O[(size_t)(ny0 + threadIdx.y + i * 8) * cHS + nx] = tile[threadIdx.x][threadIdx.y + i * 8];
}

// ===========================================================================
// Pattern selector (deterministic two-stage column mean)
// ===========================================================================
__global__ void qmean_partial(const float* __restrict__ query)
{
    const int b = blockIdx.y, tile = blockIdx.x;
    const int t = threadIdx.x;
    const int r0 = tile * 128;
    float s1 = 0.f, s2 = 0.f;
    for (int r = 0; r < 128; r++) {
        const float* base = query + ((size_t)b * cS + r0 + r) * cHS;
        s1 += base[t];
        s2 += base[t + 512];
    }
    g_qpart[(b * 16 + tile) * cHS + t] = s1;
    g_qpart[(b * 16 + tile) * cHS + t + 512] = s2;
}

__global__ __launch_bounds__(512)
void pattern_kernel(const float* __restrict__ Wp1, const float* __restrict__ bp1,
                    const float* __restrict__ Wp2, const float* __restrict__ bp2,
                    const float* __restrict__ patterns)
{
    const int b = blockIdx.x;
    const int t = threadIdx.x;
    __shared__ float qm[cHS];
    __shared__ float hb[cHS / 2];
    __shared__ float pw[cNP];
    for (int c = t; c < cHS; c += 512) {
        float s = 0.f;
        for (int p = 0; p < 16; p++) s += g_qpart[(b * 16 + p) * cHS + c];
        qm[c] = s * (1.0f / cS);
    }
    __syncthreads();
    {
        float a = bp1[t];
        for (int c = 0; c < cHS; c++) a += qm[c] * Wp1[c * (cHS / 2) + t];
        hb[t] = fmaxf(a, 0.f);
    }
    __syncthreads();
    __shared__ float lg[cNP];
    if (t < cNP) {
        float a = bp2[t];
        for (int j = 0; j < cHS / 2; j++) a += hb[j] * Wp2[j * cNP + t];
        lg[t] = a;
    }
    __syncthreads();
    if (t == 0) {
        float mx = lg[0];
        for (int p = 1; p < cNP; p++) mx = fmaxf(mx, lg[p]);
        float s = 0.f;
        for (int p = 0; p < cNP; p++) { pw[p] = __expf(lg[p] - mx); s += pw[p]; }
        float inv = 1.0f / s;
        for (int p = 0; p < cNP; p++) pw[p] *= inv;
    }
    __syncthreads();
    if (t < cNH) {
        float a = 0.f;
        for (int p = 0; p < cNP; p++) a += pw[p] * patterns[p * cNH + t];
        g_pat[b * cNH + t] = a;
    }
}

// ===========================================================================
// kernel_launch
// ===========================================================================
extern "C" void kernel_launch(void* const* d_in, const int* in_sizes, int n_in,
                              void* d_out, int out_size)
{
    const float* query = (const float*)d_in[0];
    const float* key   = (const float*)d_in[1];
    const float* value = (const float*)d_in[2];
    const int*   mask  = (const int*)d_in[3];
    const float* Wq  = (const float*)d_in[4];  const float* bq  = (const float*)d_in[5];
    const float* Wk  = (const float*)d_in[6];  const float* bk  = (const float*)d_in[7];
    const float* Wv  = (const float*)d_in[8];  const float* bv  = (const float*)d_in[9];
    const float* Wo  = (const float*)d_in[10]; const float* bo  = (const float*)d_in[11];
    const float* Wp1 = (const float*)d_in[12]; const float* bp1 = (const float*)d_in[13];
    const float* Wp2 = (const float*)d_in[14]; const float* bp2 = (const float*)d_in[15];
    const float* patterns = (const float*)d_in[16];
    float* out = (float*)d_out;

    void *pQ, *pK, *pV, *pCtx, *pWT;
    cudaGetSymbolAddress(&pQ, g_Q);
    cudaGetSymbolAddress(&pK, g_K);
    cudaGetSymbolAddress(&pV, g_V);
    cudaGetSymbolAddress(&pCtx, g_ctx);
    cudaGetSymbolAddress(&pWT, g_WT);
    const float* WT = (const float*)pWT;

    float* attn;
    if ((long)out_size >= OUT_ELEMS + ATTN_ELEMS) {
        attn = out + OUT_ELEMS;
    } else {
        void* pa;
        cudaGetSymbolAddress(&pa, g_attn_fallback);
        attn = (float*)pa;
    }

    const int SM_GEMM   = 4 * 128 * 36 * 4;                   // 73728
    const int SM_SCORES = 2 * 128 * 68 * 4;                   // 69632
    const int SM_CTX    = (2 * 128 * 36 + 2 * 64 * 36) * 4;   // 55296
    cudaFuncSetAttribute(gemm_mma<0>, cudaFuncAttributeMaxDynamicSharedMemorySize, SM_GEMM);
    cudaFuncSetAttribute(gemm_mma<1>, cudaFuncAttributeMaxDynamicSharedMemorySize, SM_GEMM);
    cudaFuncSetAttribute(scores_mma,  cudaFuncAttributeMaxDynamicSharedMemorySize, SM_SCORES);
    cudaFuncSetAttribute(context_mma, cudaFuncAttributeMaxDynamicSharedMemorySize, SM_CTX);

    // 1. pattern selector
    qmean_partial<<<dim3(16, cB), 512>>>(query);
    pattern_kernel<<<cB, 512>>>(Wp1, bp1, Wp2, bp2, patterns);

    // 2. transpose weights (Wq, Wk, Wv, Wo)
    transpose_w<<<dim3(32, 32, 4), dim3(32, 8)>>>(Wq, Wk, Wv, Wo);

    // 3. QKV projections -> [B,NH,S,HD]
    dim3 gProj(cHS / 128, (cB * cS) / 128);  // (8, 32)
    gemm_mma<1><<<gProj, 256, SM_GEMM>>>(query, WT + 0L * cHS * cHS, bq, (float*)pQ);
    gemm_mma<1><<<gProj, 256, SM_GEMM>>>(key,   WT + 1L * cHS * cHS, bk, (float*)pK);
    gemm_mma<1><<<gProj, 256, SM_GEMM>>>(value, WT + 2L * cHS * cHS, bv, (float*)pV);

    // 4. scores
    dim3 gScores(cS / 128, cS / 128, cB * cNH);  // (16, 16, 32)
    scores_mma<<<gScores, 256, SM_SCORES>>>(mask, attn);

    // 5. softmax
    softmax_k<<<cB * cNH * cS, 256>>>(attn);

    // 6. context
    dim3 gCtx(cS / 128, cB * cNH);  // (16, 32)
    context_mma<<<gCtx, 256, SM_CTX>>>(attn);

    // 7. output projection
    dim3 gOut(cHS / 128, (cB * cS) / 128);
    gemm_mma<0><<<gOut, 256, SM_GEMM>>>((const float*)pCtx, WT + 3L * cHS * cHS, bo, out);
}